// round 15
// baseline (speedup 1.0000x reference)
#include <cuda_runtime.h>
#include <cstdint>

#define NB   64
#define N    256
#define ND   511
#define RING 256
#define RMASK 255
#define BIGV 1e10f

// Diag-major: X[b][d][j] = cell (i=d-j, j).
__device__ float g_Dd[NB * ND * N];
__device__ float g_Wl[NB * ND * N];
__device__ float g_Wd[NB * ND * N];
__device__ float g_Wu[NB * ND * N];
__device__ float g_Ed[NB * ND * N];
__device__ float g_Es[ND * N];

// ---- atomic-visibility smem mailbox ops (single vector volatile access) ----
__device__ __forceinline__ void st64s(uint2* p, float z, unsigned tag) {
    unsigned a = (unsigned)__cvta_generic_to_shared(p);
    asm volatile("st.volatile.shared.v2.u32 [%0],{%1,%2};"
                 :: "r"(a), "r"(__float_as_uint(z)), "r"(tag) : "memory");
}
__device__ __forceinline__ uint2 ld64s(const uint2* p) {
    unsigned a = (unsigned)__cvta_generic_to_shared((void*)p); uint2 v;
    asm volatile("ld.volatile.shared.v2.u32 {%0,%1},[%2];"
                 : "=r"(v.x), "=r"(v.y) : "r"(a) : "memory");
    return v;
}
__device__ __forceinline__ void st128s(uint4* p, float e, float wl, float wd, unsigned tag) {
    unsigned a = (unsigned)__cvta_generic_to_shared(p);
    asm volatile("st.volatile.shared.v4.u32 [%0],{%1,%2,%3,%4};"
                 :: "r"(a), "r"(__float_as_uint(e)), "r"(__float_as_uint(wl)),
                    "r"(__float_as_uint(wd)), "r"(tag) : "memory");
}
__device__ __forceinline__ uint4 ld128s(const uint4* p) {
    unsigned a = (unsigned)__cvta_generic_to_shared((void*)p); uint4 v;
    asm volatile("ld.volatile.shared.v4.u32 {%0,%1,%2,%3},[%4];"
                 : "=r"(v.x), "=r"(v.y), "=r"(v.z), "=r"(v.w) : "r"(a) : "memory");
    return v;
}

// ---------------------------------------------------------------------------
__global__ void shear_kernel(const float* __restrict__ D) {
    __shared__ float s[32][33];
    const int b = blockIdx.z, i0 = blockIdx.y * 32, j0 = blockIdx.x * 32;
    const int tx = threadIdx.x, ty = threadIdx.y;
    const float* Db = D + (size_t)b * N * N;
    #pragma unroll
    for (int r = ty; r < 32; r += 8) s[r][tx] = Db[(i0 + r) * N + j0 + tx];
    __syncthreads();
    float* out = g_Dd + (size_t)b * ND * N;
    for (int dd = ty; dd < 63; dd += 8) {
        int r = dd - tx;
        if (r >= 0 && r < 32) out[(i0 + j0 + dd) * N + (j0 + tx)] = s[r][tx];
    }
}

__global__ void noop_kernel() {}   // spacers: keep dp_kernel at ncu launch idx 3

// ---------------------------------------------------------------------------
// Barrier-free, depth-optimal DP. One CTA per batch; thread j = column j.
// Warp w loops only its active window d in [32w, 32w+286] (wavefront skew is
// in the loop bounds). j-1 -> j via shfl inside warps; across the 7 warp
// boundaries via tagged smem ring mailboxes (1-step skew). No __syncthreads
// after init. All per-cell float ops bit-identical to the R4 passing kernel.
// ---------------------------------------------------------------------------
__global__ __launch_bounds__(256) void dp_kernel() {
    __shared__ uint2 mbF[7][RING];   // fwd: z of col 32w+31 @ step d -> slot d&255, tag d+1
    __shared__ uint4 mbB[7][RING];   // bwd: (E,Wl,Wd) of col 32(w+1) @ step d -> tag d+1

    const int b = blockIdx.x;
    const size_t base = (size_t)b * ND * N;
    const float* __restrict__ Dd = g_Dd + base;
    float* __restrict__ Wl = g_Wl + base;
    float* __restrict__ Wd = g_Wd + base;
    float* __restrict__ Wu = g_Wu + base;
    float* __restrict__ Ed = g_Ed + base;

    const int j = threadIdx.x, w = j >> 5, lane = j & 31;
    const unsigned FULL = 0xffffffffu;
    const float ZBIG  = __fdiv_rn(-BIGV, 0.01f);
    const float ZZERO = __fdiv_rn(-0.0f, 0.01f);

    // init mailboxes (tags 0 = empty), single barrier of the whole kernel
    for (int k = j; k < 7 * RING; k += 256) {
        ((uint2*)mbF)[k] = make_uint2(0u, 0u);
        ((uint4*)mbB)[k] = make_uint4(0u, 0u, 0u, 0u);
    }
    __syncthreads();

    const int d0 = 32 * w, d1 = d0 + 286;

    // ================= forward =================
    {
        float z1 = ZBIG, z2 = ZBIG, mzc = ZBIG;      // mzc: carried F[w-1][d-2]
        float th = Dd[(size_t)d0 * N + j];
        for (int d = d0; d <= d1; ++d) {
            float thn = 0.0f;
            if (d + 1 < ND) thn = Dd[(size_t)(d + 1) * N + j];

            const int i = d - j;
            const bool act = ((unsigned)i < 256u);

            float mzl = ZBIG;
            if (lane == 0 && w > 0 && act) {          // need z(d-1, 32w-1)
                uint2 m;
                do { m = ld64s(&mbF[w - 1][(d - 1) & RMASK]); } while (m.y != (unsigned)d);
                mzl = __uint_as_float(m.x);
            }
            float zl = __shfl_up_sync(FULL, z1, 1);   // z(d-1, j-1)
            float zd = __shfl_up_sync(FULL, z2, 1);   // z(d-2, j-1)
            if (lane == 0) { zl = (w > 0) ? mzl : ZBIG; zd = (w > 0) ? mzc : ZBIG; }
            float zu = z1;                            // z(d-1, j)
            if (i == 0) { zu = ZBIG; zd = (j == 0) ? ZZERO : ZBIG; }

            // --- R4-exact softmin cell ---
            const float zmax = fmaxf(fmaxf(zl, zd), zu);
            const float el = expf(__fsub_rn(zl, zmax));
            const float ed = expf(__fsub_rn(zd, zmax));
            const float eu = expf(__fsub_rn(zu, zmax));
            const float ssum = __fadd_rn(__fadd_rn(el, ed), eu);
            const float lse  = __fadd_rn(logf(ssum), zmax);
            const float R    = __fadd_rn(th, __fmul_rn(-0.01f, lse));
            const float zc   = __fdiv_rn(-R, 0.01f);

            if (act) {
                if (lane == 31 && w < 7)
                    st64s(&mbF[w][d & RMASK], zc, (unsigned)(d + 1));
                const size_t o = (size_t)d * N + j;
                Wl[o] = expf(__fsub_rn(zl, lse));
                Wd[o] = expf(__fsub_rn(zd, lse));
                Wu[o] = expf(__fsub_rn(zu, lse));
            }
            z2 = z1; z1 = act ? zc : ZBIG;
            if (lane == 0) mzc = mzl;
            th = thn;
        }
    }
    // no CTA barrier: fwd->bwd transition is per-warp; cross-warp data flows
    // exclusively through the bwd mailboxes (producer registers), so there is
    // no cross-warp gmem dependency.

    // ================= backward =================
    {
        float e1 = 0.f, e2 = 0.f;
        float wl1 = 0.f, wu1 = 0.f, wd1 = 0.f, wd2 = 0.f;
        float mE2 = 0.f, mWd2 = 0.f;                 // carried mailbox slot d+2
        // own W stream at current diag (1-deep prefetch)
        float wl0 = Wl[(size_t)d1 * N + j];
        float wd0 = Wd[(size_t)d1 * N + j];
        float wu0 = Wu[(size_t)d1 * N + j];

        for (int d = d1; d >= d0; --d) {
            float wlN = 0.f, wdN = 0.f, wuN = 0.f;
            if (d - 1 >= 0) {
                wlN = Wl[(size_t)(d - 1) * N + j];
                wdN = Wd[(size_t)(d - 1) * N + j];
                wuN = Wu[(size_t)(d - 1) * N + j];
            }

            const int i = d - j;
            const bool act = ((unsigned)i < 256u);

            float mE1 = 0.f, mWl1 = 0.f;
            if (lane == 31 && w < 7 && act) {         // need (E,Wl)(d+1, j+1)
                uint4 m;
                do { m = ld128s(&mbB[w][(d + 1) & RMASK]); } while (m.w != (unsigned)(d + 2));
                mE1 = __uint_as_float(m.x);
                mWl1 = __uint_as_float(m.y);
                // m.z = Wd(d+1, j+1) -> becomes mWd2 for next step (slot d+2 carry handled below)
                e2 = e2;  // no-op
                // stash Wd of this slot for NEXT step's d+2 use via carry:
            }
            float sE1  = __shfl_down_sync(FULL, e1, 1);
            float sE2  = __shfl_down_sync(FULL, e2, 1);
            float sWl1 = __shfl_down_sync(FULL, wl1, 1);
            float sWd2 = __shfl_down_sync(FULL, wd2, 1);
            if (lane == 31) { sE1 = mE1; sE2 = mE2; sWl1 = mWl1; sWd2 = mWd2; }

            float e = 0.f;
            if (act) {
                const bool jlt = (j < 255);
                const bool ilt = (i < 255);
                const float t0 = jlt          ? __fmul_rn(sWl1, sE1) : 0.f;
                const float t1 = (jlt && ilt) ? __fmul_rn(sWd2, sE2) : 0.f;
                const float t2 = ilt          ? __fmul_rn(wu1,  e1)  : 0.f;
                e = __fadd_rn(__fadd_rn(t0, t1), t2);
                if (i == 255 && j == 255) e = 1.0f;
                if (lane == 0 && w > 0)
                    st128s(&mbB[w - 1][d & RMASK], e, wl0, wd0, (unsigned)(d + 1));
                Ed[(size_t)d * N + j] = e;
            }
            e2 = e1; e1 = act ? e : 0.f;
            wd2 = wd1; wd1 = wd0; wl1 = wl0; wu1 = wu0;
            wl0 = wlN; wd0 = wdN; wu0 = wuN;
            if (lane == 31 && w < 7) {
                // carry: slot (d+1)'s E and Wd serve as (d+2)-values next step
                mE2 = mE1;
                // re-read of m.z avoided: recompute from last ld128s result
            }
            // mWd2 carry: the Wd stored in slot d+1 (read this step) is Wd(d+1, j+1)
            // -> next step (d-1) needs Wd(d+1, j+1) as its "d+2" value.
            if (lane == 31 && w < 7 && act) {
                uint4 m2 = ld128s(&mbB[w][(d + 1) & RMASK]);  // tag already verified
                mWd2 = __uint_as_float(m2.z);
            }
        }
    }
}

// ---------------------------------------------------------------------------
__global__ void reduce_kernel() {
    const int idx = blockIdx.x * blockDim.x + threadIdx.x;
    float s = 0.0f;
    #pragma unroll 4
    for (int b = 0; b < NB; ++b) s += g_Ed[(size_t)b * ND * N + idx];
    g_Es[idx] = s * (1.0f / NB);
}
__global__ void gather_kernel(float* __restrict__ out) {
    const int idx = blockIdx.x * blockDim.x + threadIdx.x;
    const int i = idx >> 8, j = idx & (N - 1);
    out[idx] = g_Es[(i + j) * N + j];
}

// ---------------------------------------------------------------------------
extern "C" void kernel_launch(void* const* d_in, const int* in_sizes, int n_in,
                              void* d_out, int out_size) {
    const float* D = (const float*)d_in[0];
    float* out = (float*)d_out;

    shear_kernel<<<dim3(8, 8, NB), dim3(32, 8)>>>(D);   // launch 0
    noop_kernel<<<1, 32>>>();                           // launch 1 (spacer)
    noop_kernel<<<1, 32>>>();                           // launch 2 (spacer)
    dp_kernel<<<NB, 256>>>();                           // launch 3  <- ncu target
    reduce_kernel<<<ND, 256>>>();                       // launch 4
    gather_kernel<<<(N * N) / 256, 256>>>(out);         // launch 5
}

// round 16
// speedup vs baseline: 2.4428x; 2.4428x over previous
#include <cuda_runtime.h>

#define NB   64
#define N    256
#define ND   511          // number of anti-diagonals (2N-1)
#define BIGV 1e10f

// Scratch (device globals; no allocations allowed).
// Diag-major layout: X[b][d][j] = cell (i=d-j, j) of batch b.
__device__ float g_Dd[NB * ND * N];   // sheared input costs
__device__ float g_Wl[NB * ND * N];   // softmin weight w_left  per cell
__device__ float g_Wd[NB * ND * N];   // softmin weight w_diag  per cell
__device__ float g_Wu[NB * ND * N];   // softmin weight w_up    per cell
__device__ float g_Ed[NB * ND * N];   // per-batch E
__device__ float g_Es[ND * N];        // batch-mean E (diag-major)

// ---------------------------------------------------------------------------
// Shear: row-major D -> diag-major g_Dd, coalesced both ways via smem tiles.
// ---------------------------------------------------------------------------
__global__ void shear_kernel(const float* __restrict__ D) {
    __shared__ float s[32][33];
    const int b  = blockIdx.z;
    const int i0 = blockIdx.y * 32;
    const int j0 = blockIdx.x * 32;
    const int tx = threadIdx.x, ty = threadIdx.y;

    const float* Db = D + (size_t)b * N * N;
    #pragma unroll
    for (int r = ty; r < 32; r += 8)
        s[r][tx] = Db[(i0 + r) * N + j0 + tx];
    __syncthreads();

    float* out = g_Dd + (size_t)b * ND * N;
    for (int dd = ty; dd < 63; dd += 8) {
        int r = dd - tx;
        if (r >= 0 && r < 32)
            out[(i0 + j0 + dd) * N + (j0 + tx)] = s[r][tx];
    }
}

// ---------------------------------------------------------------------------
// Fused forward + backward DP. One CTA per batch, thread j = column j.
// EXACT champion-R4 values and op order. The only changes vs R4:
//   (1) the 3 weight expf + 3 stores are deferred past the __syncthreads
//       (inputs kept in registers; identical ops on identical values, issued
//       in the next step's latency shadow instead of before barrier arrival);
//   (2) depth-2 scalar prefetch on the streamed th / W loads.
// ---------------------------------------------------------------------------
__global__ __launch_bounds__(256) void dp_kernel() {
    __shared__ float sb[10][N];

    const int b = blockIdx.x;
    const size_t base = (size_t)b * ND * N;
    const float* __restrict__ Dd = g_Dd + base;
    float* __restrict__ Wl = g_Wl + base;
    float* __restrict__ Wd = g_Wd + base;
    float* __restrict__ Wu = g_Wu + base;
    float* __restrict__ Ed = g_Ed + base;

    const int j = threadIdx.x;
    const bool jgt0 = (j > 0);
    const bool jlt  = (j < N - 1);

    // ---------------- forward ----------------
    {
        float *rcur = sb[0], *rp1 = sb[1], *rp2 = sb[2];
        float th0 = Dd[j];                              // depth-2 prefetch
        float th1 = Dd[N + j];
        // pending-weight registers (deferred past the barrier)
        bool  p_act = false;
        int   p_d   = 0;
        float p_zl = 0.f, p_zd = 0.f, p_zu = 0.f, p_lse = 0.f;

        for (int d = 0; d < ND; ++d) {
            float thN = 0.0f;
            if (d + 2 < ND) thN = Dd[(size_t)(d + 2) * N + j];

            // flush previous step's weights (off the barrier-arrival path:
            // overlaps this step's LDS/compute latency)
            if (p_act) {
                const size_t o = (size_t)p_d * N + j;
                Wl[o] = expf(__fsub_rn(p_zl, p_lse));
                Wd[o] = expf(__fsub_rn(p_zd, p_lse));
                Wu[o] = expf(__fsub_rn(p_zu, p_lse));
            }

            const int i = d - j;
            const bool act = ((unsigned)i < (unsigned)N);
            if (act) {
                const float vl = jgt0    ? rp1[j - 1] : BIGV;          // R[i][j-1]
                const float vu = (i > 0) ? rp1[j]     : BIGV;          // R[i-1][j]
                float vd;                                              // R[i-1][j-1]
                if (i > 0 && jgt0)       vd = rp2[j - 1];
                else                     vd = (i == 0 && j == 0) ? 0.0f : BIGV;

                const float zl = __fdiv_rn(-vl, 0.01f);
                const float zd = __fdiv_rn(-vd, 0.01f);
                const float zu = __fdiv_rn(-vu, 0.01f);
                const float zmax = fmaxf(fmaxf(zl, zd), zu);
                const float el = expf(__fsub_rn(zl, zmax));
                const float ed = expf(__fsub_rn(zd, zmax));
                const float eu = expf(__fsub_rn(zu, zmax));
                const float ssum = __fadd_rn(__fadd_rn(el, ed), eu);
                const float lse  = __fadd_rn(logf(ssum), zmax);
                const float minv = __fmul_rn(-0.01f, lse);
                const float R    = __fadd_rn(th0, minv);
                rcur[j] = R;

                p_zl = zl; p_zd = zd; p_zu = zu; p_lse = lse; p_d = d;
            }
            p_act = act;
            __syncthreads();
            th0 = th1; th1 = thN;
            float* t = rp2; rp2 = rp1; rp1 = rcur; rcur = t;
        }
        // epilogue: flush last pending weights
        if (p_act) {
            const size_t o = (size_t)p_d * N + j;
            Wl[o] = expf(__fsub_rn(p_zl, p_lse));
            Wd[o] = expf(__fsub_rn(p_zd, p_lse));
            Wu[o] = expf(__fsub_rn(p_zu, p_lse));
        }
    }
    __syncthreads();

    // ---------------- backward (R4 values; depth-2 W prefetch) ----------------
    {
        float *ecur = sb[0], *ep1 = sb[1], *ep2 = sb[2];
        float *qlc  = sb[3], *qlp = sb[4];                  // w_left  (cur, d+1)
        float *quc  = sb[5], *qup = sb[6];                  // w_up    (cur, d+1)
        float *qdc  = sb[7], *qdp1 = sb[8], *qdp2 = sb[9];  // w_diag  (cur, d+1, d+2)

        // depth-2 pipeline: slot0 = W(d), slot1 = W(d-1)
        float wl0 = Wl[(size_t)(ND - 1) * N + j];
        float wd0 = Wd[(size_t)(ND - 1) * N + j];
        float wu0 = Wu[(size_t)(ND - 1) * N + j];
        float wl1 = Wl[(size_t)(ND - 2) * N + j];
        float wd1p = Wd[(size_t)(ND - 2) * N + j];
        float wu1p = Wu[(size_t)(ND - 2) * N + j];

        for (int d = ND - 1; d >= 0; --d) {
            float wlN = 0.0f, wdN = 0.0f, wuN = 0.0f;
            if (d - 2 >= 0) {
                wlN = Wl[(size_t)(d - 2) * N + j];
                wdN = Wd[(size_t)(d - 2) * N + j];
                wuN = Wu[(size_t)(d - 2) * N + j];
            }

            const int i = d - j;
            if ((unsigned)i < (unsigned)N) {
                float e;
                if (i == N - 1 && j == N - 1) {
                    e = 1.0f;
                } else {
                    float t0 = 0.0f, t1 = 0.0f, t2 = 0.0f;
                    if (jlt)                       // from (i, j+1)  @ diag d+1
                        t0 = __fmul_rn(qlp[j + 1], ep1[j + 1]);
                    if (i < N - 1) {
                        if (jlt)                   // from (i+1,j+1) @ diag d+2
                            t1 = __fmul_rn(qdp2[j + 1], ep2[j + 1]);
                        t2 = __fmul_rn(qup[j], ep1[j]);   // from (i+1, j) @ d+1
                    }
                    e = __fadd_rn(__fadd_rn(t0, t1), t2);
                }
                Ed[(size_t)d * N + j] = e;
                ecur[j] = e;
                qlc[j] = wl0;
                quc[j] = wu0;
                qdc[j] = wd0;
            }
            __syncthreads();
            wl0 = wl1;  wd0 = wd1p; wu0 = wu1p;
            wl1 = wlN;  wd1p = wdN; wu1p = wuN;
            float* t;
            t = ep2;  ep2  = ep1;  ep1 = ecur; ecur = t;
            t = qlp;  qlp  = qlc;  qlc = t;
            t = qup;  qup  = quc;  quc = t;
            t = qdp2; qdp2 = qdp1; qdp1 = qdc; qdc = t;
        }
    }
}

// ---------------------------------------------------------------------------
__global__ void reduce_kernel() {
    const int idx = blockIdx.x * blockDim.x + threadIdx.x;   // < ND*N
    float s = 0.0f;
    #pragma unroll 4
    for (int b = 0; b < NB; ++b) s += g_Ed[(size_t)b * ND * N + idx];
    g_Es[idx] = s * (1.0f / NB);
}

__global__ void gather_kernel(float* __restrict__ out) {
    const int idx = blockIdx.x * blockDim.x + threadIdx.x;   // < N*N
    const int i = idx >> 8, j = idx & (N - 1);
    out[idx] = g_Es[(i + j) * N + j];
}

// ---------------------------------------------------------------------------
extern "C" void kernel_launch(void* const* d_in, const int* in_sizes, int n_in,
                              void* d_out, int out_size) {
    const float* D = (const float*)d_in[0];
    float* out = (float*)d_out;

    shear_kernel<<<dim3(8, 8, NB), dim3(32, 8)>>>(D);
    dp_kernel<<<NB, 256>>>();
    reduce_kernel<<<ND, 256>>>();
    gather_kernel<<<(N * N) / 256, 256>>>(out);
}